// round 15
// baseline (speedup 1.0000x reference)
#include <cuda_runtime.h>

#define N_NODES 100000
#define N_EDGES 1000000
#define F_IN 15
#define H 64
#define EMB 128
#define NREL 13
#define NB 4

typedef unsigned long long u64;

// packed-f32x2 helpers (sm_100+ PTX; ptxas never emits FFMA2 from C++)
__device__ __forceinline__ u64 bcast2(float x) {
    unsigned u = __float_as_uint(x);
    u64 r;
    asm("mov.b64 %0, {%1, %1};" : "=l"(r) : "r"(u));
    return r;
}
__device__ __forceinline__ void fma2(u64& c, u64 a, u64 b) {
    asm("fma.rn.f32x2 %0, %1, %2, %3;" : "=l"(c) : "l"(a), "l"(b), "l"(c));
}
__device__ __forceinline__ void unpack2(u64 v, float& lo, float& hi) {
    unsigned l, h;
    asm("mov.b64 {%0, %1}, %2;" : "=r"(l), "=r"(h) : "l"(v));
    lo = __uint_as_float(l);
    hi = __uint_as_float(h);
}

// ---------------- scratch (no allocations allowed) ----------------
__device__ float g_A[N_NODES * H];          // 25.6 MB  (h buffers)
__device__ float g_B[N_NODES * H];          // 25.6 MB
__device__ float g_M[N_NODES * H * NB];     // 102.4 MB (pre-aggregated basis sums)
__device__ float g_psum[256 * H];
__device__ float g_pmax[256 * H];
__device__ int   g_cnt[N_NODES];
__device__ int   g_row[N_NODES];
__device__ int   g_cur[N_NODES];
__device__ int   g_elist[N_EDGES];          // packed: src | (etype<<17)

// ---------------- CSR build ----------------
__global__ void k_zero(int* __restrict__ cnt) {
    int i = blockIdx.x * 256 + threadIdx.x;
    if (i < N_NODES) cnt[i] = 0;
}

__global__ void k_hist(const int* __restrict__ tgt, int* __restrict__ cnt) {
    int e = blockIdx.x * 256 + threadIdx.x;
    if (e < N_EDGES) atomicAdd(&cnt[tgt[e]], 1);
}

__global__ void k_scan(const int* __restrict__ cnt, int* __restrict__ row,
                       int* __restrict__ cur) {
    const int CH = (N_NODES + 1023) / 1024;
    __shared__ int sp[1024];
    int tid = threadIdx.x;
    int start = tid * CH;
    int s = 0;
    for (int i = 0; i < CH; i++) {
        int idx = start + i;
        if (idx < N_NODES) s += cnt[idx];
    }
    sp[tid] = s;
    __syncthreads();
    for (int off = 1; off < 1024; off <<= 1) {
        int v = 0;
        if (tid >= off) v = sp[tid - off];
        __syncthreads();
        if (tid >= off) sp[tid] += v;
        __syncthreads();
    }
    int run = (tid == 0) ? 0 : sp[tid - 1];
    for (int i = 0; i < CH; i++) {
        int idx = start + i;
        if (idx < N_NODES) {
            row[idx] = run;
            cur[idx] = run;
            run += cnt[idx];
        }
    }
}

__global__ void k_scatter(const int* __restrict__ src, const int* __restrict__ tgt,
                          const int* __restrict__ et, int* __restrict__ cur,
                          int* __restrict__ elist) {
    int e = blockIdx.x * 256 + threadIdx.x;
    if (e >= N_EDGES) return;
    int t = tgt[e];
    int pos = atomicAdd(&cur[t], 1);
    elist[pos] = src[e] | (et[e] << 17);
}

// ---------------- input projection: h0 = nf @ W_in + b_in ----------------
__global__ void k_inproj(const float* __restrict__ nf, const float* __restrict__ W,
                         const float* __restrict__ b, float* __restrict__ out) {
    __shared__ float sW[F_IN * H];
    __shared__ float sb[H];
    __shared__ float snf[4 * F_IN];
    int tid = threadIdx.x;
    for (int i = tid; i < F_IN * H; i += 256) sW[i] = W[i];
    if (tid < H) sb[tid] = b[tid];
    int n0 = blockIdx.x * 4;
    if (tid < 4 * F_IN) {
        int g = n0 * F_IN + tid;
        snf[tid] = (g < N_NODES * F_IN) ? nf[g] : 0.f;
    }
    __syncthreads();
    int lr = tid >> 6, col = tid & 63;
    int node = n0 + lr;
    if (node < N_NODES) {
        float acc = sb[col];
#pragma unroll
        for (int k = 0; k < F_IN; k++) acc = fmaf(snf[lr * F_IN + k], sW[k * H + col], acc);
        out[node * H + col] = acc;
    }
}

// ---------------- pre-aggregation over edges (4-way unrolled) ----------------
// m[t, b, :] = sum_{e in in(t)} coeffs[etype(e), b] * act(h[src(e), :])
__global__ void k_edges_pre(const int* __restrict__ row, const int* __restrict__ cnt,
                            const int* __restrict__ elist, const float* __restrict__ coeffs,
                            const float* __restrict__ h, int relu_in,
                            float* __restrict__ m) {
    __shared__ float sc[NREL * NB];
    int tid = threadIdx.x;
    if (tid < NREL * NB) sc[tid] = coeffs[tid];
    __syncthreads();

    int lane = tid & 63;
    int t = blockIdx.x * 4 + (tid >> 6);
    if (t >= N_NODES) return;
    int beg = __ldg(&row[t]);
    int deg = __ldg(&cnt[t]);

    float a0[NB] = {}, a1[NB] = {}, a2[NB] = {}, a3[NB] = {};
    int i = 0;
    for (; i + 4 <= deg; i += 4) {
        int pk0 = __ldg(&elist[beg + i]);
        int pk1 = __ldg(&elist[beg + i + 1]);
        int pk2 = __ldg(&elist[beg + i + 2]);
        int pk3 = __ldg(&elist[beg + i + 3]);
        float v0 = __ldg(&h[(pk0 & 0x1FFFF) * H + lane]);
        float v1 = __ldg(&h[(pk1 & 0x1FFFF) * H + lane]);
        float v2 = __ldg(&h[(pk2 & 0x1FFFF) * H + lane]);
        float v3 = __ldg(&h[(pk3 & 0x1FFFF) * H + lane]);
        if (relu_in) {
            v0 = fmaxf(v0, 0.f); v1 = fmaxf(v1, 0.f);
            v2 = fmaxf(v2, 0.f); v3 = fmaxf(v3, 0.f);
        }
        const float* c0 = sc + (pk0 >> 17) * NB;
        const float* c1 = sc + (pk1 >> 17) * NB;
        const float* c2 = sc + (pk2 >> 17) * NB;
        const float* c3 = sc + (pk3 >> 17) * NB;
#pragma unroll
        for (int b = 0; b < NB; b++) {
            a0[b] = fmaf(c0[b], v0, a0[b]);
            a1[b] = fmaf(c1[b], v1, a1[b]);
            a2[b] = fmaf(c2[b], v2, a2[b]);
            a3[b] = fmaf(c3[b], v3, a3[b]);
        }
    }
    for (; i < deg; i++) {
        int pk = __ldg(&elist[beg + i]);
        float v = __ldg(&h[(pk & 0x1FFFF) * H + lane]);
        if (relu_in) v = fmaxf(v, 0.f);
        const float* cf = sc + (pk >> 17) * NB;
#pragma unroll
        for (int b = 0; b < NB; b++) a0[b] = fmaf(cf[b], v, a0[b]);
    }
    float* mt = m + (size_t)t * (H * NB);
#pragma unroll
    for (int b = 0; b < NB; b++) mt[b * H + lane] = (a0[b] + a1[b]) + (a2[b] + a3[b]);
}

// ---------------- fused layer GEMM (128 thr, 8x8 microtile, f32x2) ----------------
// out = act(hin) @ Wself + bself + sum_b m[:,b,:] @ bases[b]
__global__ void __launch_bounds__(128)
k_layer(const float* __restrict__ hin, int relu_in,
        const float* __restrict__ m,
        const float* __restrict__ Wself, const float* __restrict__ bself,
        const float* __restrict__ bases,
        float* __restrict__ out) {
    __shared__ float sA[H][132];   // transposed: sA[k][row], 128 rows; stride 528B (16B-aligned)
    __shared__ float sB[H][68];
    int tid = threadIdx.x;         // 128
    int n0 = blockIdx.x * 128;
    int tx = tid & 7, ty = tid >> 3;   // 8 cols x 8 rows per thread

    u64 c2[4][8] = {};             // 4 packed row-pairs x 8 cols

    int node_s = n0 + tid;         // staging row for this thread
    bool okn = node_s < N_NODES;

    for (int ch = 0; ch < 5; ch++) {
        // ---- stage A (conflict-free: lanes write consecutive rows) ----
        if (ch == 0) {
            const float* hrow = hin + (size_t)node_s * H;
#pragma unroll
            for (int it = 0; it < 16; it++) {
                float4 v = {0.f, 0.f, 0.f, 0.f};
                if (okn) v = *(const float4*)&hrow[it * 4];
                if (relu_in) {
                    v.x = fmaxf(v.x, 0.f); v.y = fmaxf(v.y, 0.f);
                    v.z = fmaxf(v.z, 0.f); v.w = fmaxf(v.w, 0.f);
                }
                sA[it * 4 + 0][tid] = v.x;
                sA[it * 4 + 1][tid] = v.y;
                sA[it * 4 + 2][tid] = v.z;
                sA[it * 4 + 3][tid] = v.w;
            }
        } else {
            const float* mrow = m + (size_t)node_s * (H * NB) + (ch - 1) * H;
#pragma unroll
            for (int it = 0; it < 16; it++) {
                float4 v = {0.f, 0.f, 0.f, 0.f};
                if (okn) v = *(const float4*)&mrow[it * 4];
                sA[it * 4 + 0][tid] = v.x;
                sA[it * 4 + 1][tid] = v.y;
                sA[it * 4 + 2][tid] = v.z;
                sA[it * 4 + 3][tid] = v.w;
            }
        }
        // ---- stage B (vectorized) ----
        const float* Bsrc = (ch == 0) ? Wself : (bases + (ch - 1) * H * H);
#pragma unroll
        for (int i = tid; i < H * H / 4; i += 128) {
            int k = i >> 4, c4 = (i & 15) * 4;
            *(float4*)&sB[k][c4] = *(const float4*)&Bsrc[k * H + c4];
        }
        __syncthreads();

#pragma unroll 8
        for (int k = 0; k < H; k++) {
            ulonglong2 aA = *(const ulonglong2*)&sA[k][ty * 8];
            ulonglong2 aB = *(const ulonglong2*)&sA[k][ty * 8 + 4];
            float4 b0 = *(const float4*)&sB[k][tx * 8];
            float4 b1 = *(const float4*)&sB[k][tx * 8 + 4];
            u64 ap[4] = {aA.x, aA.y, aB.x, aB.y};
            u64 bb[8] = {bcast2(b0.x), bcast2(b0.y), bcast2(b0.z), bcast2(b0.w),
                         bcast2(b1.x), bcast2(b1.y), bcast2(b1.z), bcast2(b1.w)};
#pragma unroll
            for (int p = 0; p < 4; p++)
#pragma unroll
                for (int j = 0; j < 8; j++)
                    fma2(c2[p][j], ap[p], bb[j]);
        }
        __syncthreads();
    }

    int colbase = tx * 8;
    float4 bs0 = *(const float4*)&bself[colbase];
    float4 bs1 = *(const float4*)&bself[colbase + 4];
    float bias[8] = {bs0.x, bs0.y, bs0.z, bs0.w, bs1.x, bs1.y, bs1.z, bs1.w};
#pragma unroll
    for (int p = 0; p < 4; p++) {
        float lo[8], hi[8];
#pragma unroll
        for (int j = 0; j < 8; j++) unpack2(c2[p][j], lo[j], hi[j]);
        int node0 = n0 + ty * 8 + 2 * p;
        if (node0 < N_NODES) {
            float4 o0 = {lo[0] + bias[0], lo[1] + bias[1], lo[2] + bias[2], lo[3] + bias[3]};
            float4 o1 = {lo[4] + bias[4], lo[5] + bias[5], lo[6] + bias[6], lo[7] + bias[7]};
            *(float4*)&out[node0 * H + colbase] = o0;
            *(float4*)&out[node0 * H + colbase + 4] = o1;
        }
        if (node0 + 1 < N_NODES) {
            float4 o0 = {hi[0] + bias[0], hi[1] + bias[1], hi[2] + bias[2], hi[3] + bias[3]};
            float4 o1 = {hi[4] + bias[4], hi[5] + bias[5], hi[6] + bias[6], hi[7] + bias[7]};
            *(float4*)&out[(node0 + 1) * H + colbase] = o0;
            *(float4*)&out[(node0 + 1) * H + colbase + 4] = o1;
        }
    }
}

// ---------------- pooling stage 1 ----------------
__global__ void k_pool1(const float* __restrict__ hbuf) {
    int tid = threadIdx.x;
    int col = tid & 63;
    int sub = tid >> 6;
    float s = 0.f, mx = -3.4e38f;
    for (int n = blockIdx.x * 4 + sub; n < N_NODES; n += gridDim.x * 4) {
        float v = fmaxf(hbuf[n * H + col], 0.f);
        s += v;
        mx = fmaxf(mx, v);
    }
    __shared__ float ss[256], sm[256];
    ss[tid] = s; sm[tid] = mx;
    __syncthreads();
    if (sub == 0) {
        float fs = ss[col] + ss[64 + col] + ss[128 + col] + ss[192 + col];
        float fm = fmaxf(fmaxf(sm[col], sm[64 + col]), fmaxf(sm[128 + col], sm[192 + col]));
        g_psum[blockIdx.x * H + col] = fs;
        g_pmax[blockIdx.x * H + col] = fm;
    }
}

// ---------------- pooling stage 2 + readout MLP ----------------
__global__ void k_pool2(const float* __restrict__ Wr1, const float* __restrict__ br1,
                        const float* __restrict__ Wr2, const float* __restrict__ br2,
                        float* __restrict__ out, int nblocks) {
    __shared__ float g[2 * H];
    __shared__ float t[H];
    int tid = threadIdx.x;
    if (tid < H) {
        float s = 0.f, mx = -3.4e38f;
        for (int b = 0; b < nblocks; b++) {
            s += g_psum[b * H + tid];
            mx = fmaxf(mx, g_pmax[b * H + tid]);
        }
        g[tid] = s / (float)N_NODES;
        g[H + tid] = mx;
    }
    __syncthreads();
    if (tid < H) {
        float a = br1[tid];
#pragma unroll 8
        for (int i = 0; i < 2 * H; i++) a = fmaf(g[i], Wr1[i * H + tid], a);
        t[tid] = fmaxf(a, 0.f);
    }
    __syncthreads();
    if (tid < EMB) {
        float a = br2[tid];
#pragma unroll 8
        for (int j = 0; j < H; j++) a = fmaf(t[j], Wr2[j * EMB + tid], a);
        out[tid] = a;
    }
}

// ---------------- node embedding (128 thr, 8x8 microtile, f32x2) ----------------
__global__ void __launch_bounds__(128)
k_nodeemb(const float* __restrict__ hbuf, const float* __restrict__ Wnp,
          const float* __restrict__ bnp, float* __restrict__ out) {
    __shared__ float sA[H][132];
    __shared__ float sB[H][68];
    int tid = threadIdx.x;   // 128
    int n0 = blockIdx.x * 128;
    int tx = tid & 7, ty = tid >> 3;

    int node_s = n0 + tid;
    bool okn = node_s < N_NODES;
    {
        const float* hrow = hbuf + (size_t)node_s * H;
#pragma unroll
        for (int it = 0; it < 16; it++) {
            float4 v = {0.f, 0.f, 0.f, 0.f};
            if (okn) v = *(const float4*)&hrow[it * 4];
            v.x = fmaxf(v.x, 0.f); v.y = fmaxf(v.y, 0.f);
            v.z = fmaxf(v.z, 0.f); v.w = fmaxf(v.w, 0.f);
            sA[it * 4 + 0][tid] = v.x;
            sA[it * 4 + 1][tid] = v.y;
            sA[it * 4 + 2][tid] = v.z;
            sA[it * 4 + 3][tid] = v.w;
        }
    }

    for (int pass = 0; pass < 2; pass++) {
#pragma unroll
        for (int i = tid; i < H * H / 4; i += 128) {
            int k = i >> 4, c4 = (i & 15) * 4;
            *(float4*)&sB[k][c4] = *(const float4*)&Wnp[k * EMB + pass * H + c4];
        }
        __syncthreads();

        u64 c2[4][8] = {};
#pragma unroll 8
        for (int k = 0; k < H; k++) {
            ulonglong2 aA = *(const ulonglong2*)&sA[k][ty * 8];
            ulonglong2 aB = *(const ulonglong2*)&sA[k][ty * 8 + 4];
            float4 b0 = *(const float4*)&sB[k][tx * 8];
            float4 b1 = *(const float4*)&sB[k][tx * 8 + 4];
            u64 ap[4] = {aA.x, aA.y, aB.x, aB.y};
            u64 bb[8] = {bcast2(b0.x), bcast2(b0.y), bcast2(b0.z), bcast2(b0.w),
                         bcast2(b1.x), bcast2(b1.y), bcast2(b1.z), bcast2(b1.w)};
#pragma unroll
            for (int p = 0; p < 4; p++)
#pragma unroll
                for (int j = 0; j < 8; j++)
                    fma2(c2[p][j], ap[p], bb[j]);
        }

        int colbase = tx * 8;
        float4 bb0 = *(const float4*)&bnp[pass * H + colbase];
        float4 bb1 = *(const float4*)&bnp[pass * H + colbase + 4];
        float bias[8] = {bb0.x, bb0.y, bb0.z, bb0.w, bb1.x, bb1.y, bb1.z, bb1.w};
#pragma unroll
        for (int p = 0; p < 4; p++) {
            float lo[8], hi[8];
#pragma unroll
            for (int j = 0; j < 8; j++) unpack2(c2[p][j], lo[j], hi[j]);
            int node0 = n0 + ty * 8 + 2 * p;
            if (node0 < N_NODES) {
                float4 o0 = {lo[0] + bias[0], lo[1] + bias[1], lo[2] + bias[2], lo[3] + bias[3]};
                float4 o1 = {lo[4] + bias[4], lo[5] + bias[5], lo[6] + bias[6], lo[7] + bias[7]};
                *(float4*)&out[(size_t)node0 * EMB + pass * H + colbase] = o0;
                *(float4*)&out[(size_t)node0 * EMB + pass * H + colbase + 4] = o1;
            }
            if (node0 + 1 < N_NODES) {
                float4 o0 = {hi[0] + bias[0], hi[1] + bias[1], hi[2] + bias[2], hi[3] + bias[3]};
                float4 o1 = {hi[4] + bias[4], hi[5] + bias[5], hi[6] + bias[6], hi[7] + bias[7]};
                *(float4*)&out[(size_t)(node0 + 1) * EMB + pass * H + colbase] = o0;
                *(float4*)&out[(size_t)(node0 + 1) * EMB + pass * H + colbase + 4] = o1;
            }
        }
        __syncthreads();
    }
}

// ---------------- launch ----------------
extern "C" void kernel_launch(void* const* d_in, const int* in_sizes, int n_in,
                              void* d_out, int out_size) {
    const float* nf     = (const float*)d_in[0];
    const int*   ei     = (const int*)  d_in[1];
    const int*   et     = (const int*)  d_in[2];
    const float* W_in   = (const float*)d_in[3];
    const float* b_in   = (const float*)d_in[4];
    const float* Wself0 = (const float*)d_in[5];
    const float* bself0 = (const float*)d_in[6];
    const float* bases0 = (const float*)d_in[7];
    const float* coeffs0= (const float*)d_in[8];
    const float* Wself1 = (const float*)d_in[9];
    const float* bself1 = (const float*)d_in[10];
    const float* bases1 = (const float*)d_in[11];
    const float* coeffs1= (const float*)d_in[12];
    const float* Wr1    = (const float*)d_in[13];
    const float* br1    = (const float*)d_in[14];
    const float* Wr2    = (const float*)d_in[15];
    const float* br2    = (const float*)d_in[16];
    const float* Wnp    = (const float*)d_in[17];
    const float* bnp    = (const float*)d_in[18];
    float* out = (float*)d_out;

    float *A, *B, *M;
    int *cnt, *row, *cur, *elist;
    cudaGetSymbolAddress((void**)&A, g_A);
    cudaGetSymbolAddress((void**)&B, g_B);
    cudaGetSymbolAddress((void**)&M, g_M);
    cudaGetSymbolAddress((void**)&cnt, g_cnt);
    cudaGetSymbolAddress((void**)&row, g_row);
    cudaGetSymbolAddress((void**)&cur, g_cur);
    cudaGetSymbolAddress((void**)&elist, g_elist);

    const int* src = ei;
    const int* tgt = ei + N_EDGES;

    int nb128 = (N_NODES + 127) / 128;
    int nbN   = (N_NODES + 255) / 256;
    int nbE   = (N_EDGES + 255) / 256;
    int nbT4  = (N_NODES + 3) / 4;

    // CSR build (by target)
    k_zero<<<nbN, 256>>>(cnt);
    k_hist<<<nbE, 256>>>(tgt, cnt);
    k_scan<<<1, 1024>>>(cnt, row, cur);
    k_scatter<<<nbE, 256>>>(src, tgt, et, cur, elist);

    // h0 = nf @ W_in + b_in -> A
    k_inproj<<<nbT4, 256>>>(nf, W_in, b_in, A);

    // layer 0: pre-aggregate h0 into M, then fused GEMM -> B
    k_edges_pre<<<nbT4, 256>>>(row, cnt, elist, coeffs0, A, 0, M);
    k_layer<<<nb128, 128>>>(A, 0, M, Wself0, bself0, bases0, B);

    // layer 1: pre-aggregate relu(h1) into M, then fused GEMM -> A
    k_edges_pre<<<nbT4, 256>>>(row, cnt, elist, coeffs1, B, 1, M);
    k_layer<<<nb128, 128>>>(B, 1, M, Wself1, bself1, bases1, A);

    // readout: graph_emb = out[0:128]
    k_pool1<<<256, 256>>>(A);
    k_pool2<<<1, 128>>>(Wr1, br1, Wr2, br2, out, 256);

    // node_emb = out[128:]
    k_nodeemb<<<nb128, 128>>>(A, Wnp, bnp, out + EMB);
}